// round 8
// baseline (speedup 1.0000x reference)
#include <cuda_runtime.h>
#include <cuda_fp16.h>
#include <math_constants.h>

#define HH 512
#define WW 512
#define BB 16
// window p=35, pad=17, chunk=35
// loss = mean(erosion_35x35(min_c x)) - 1   (erosion = separable min filter)

// Intermediate: vertically eroded field, TRANSPOSED: [B][W][Hp] where each
// __half2 packs rows (2*hp, 2*hp+1). k2 chains walk w at fixed hp.
__device__ __align__(16) __half2 g_tT[BB * WW * (HH / 2)];
// Per-block partial sums from kernel 2 (960 blocks)
__device__ float g_partial[960];
// Completion counter for fused final reduction (reset each run)
__device__ int g_count;

// ---------------------------------------------------------------------------
// Kernel 1: channel-min of x (fp32 -> fp16) fused with vertical min-filter
// (van Herk chunk 35, half2 packed along W), then TRANSPOSED store:
// results staged in smem [w_local][h_local] as halves, written out as
// h-pair half2 coalesced along hp.
// Block = (32 lanes, 4 chunks) = 128 thr; grid = (W/64, B, 4).
// ---------------------------------------------------------------------------
__global__ __launch_bounds__(128) void k1_vert(const float* __restrict__ x) {
    __shared__ __half2 sm[174 * 32];          // input tile (22.3KB)
    __shared__ __half  st[64 * 142];          // [w_local][h_local] staging (18.2KB)

    const int tx  = threadIdx.x;
    const int ty  = threadIdx.y;
    const int tid = ty * 32 + tx;
    const int wc0 = blockIdx.x * 64;
    const int b   = blockIdx.y;
    const int z   = blockIdx.z;
    const int r0  = z * 140;                 // 4 chunks * 35 rows per z-group
    const float INF = CUDART_INF_F;

    // Load channel-min into smem rows [r0-17, r0+157), as half2 (2 W cols)
    const float* xb = x + (size_t)b * 3 * HH * WW;
    for (int j = tid; j < 174 * 16; j += 128) {
        int r  = j >> 4;
        int c4 = j & 15;                      // float4 slot within 64 cols
        int gh = r0 - 17 + r;
        float4 m;
        if ((unsigned)gh < HH) {
            const float4* p = (const float4*)(xb + (size_t)gh * WW + wc0 + c4 * 4);
            float4 a0 = p[0];
            float4 a1 = p[(HH * WW) / 4];
            float4 a2 = p[(2 * HH * WW) / 4];
            m.x = fminf(a0.x, fminf(a1.x, a2.x));
            m.y = fminf(a0.y, fminf(a1.y, a2.y));
            m.z = fminf(a0.z, fminf(a1.z, a2.z));
            m.w = fminf(a0.w, fminf(a1.w, a2.w));
        } else {
            m = make_float4(INF, INF, INF, INF);
        }
        sm[r * 32 + c4 * 2]     = __floats2half2_rn(m.x, m.y);
        sm[r * 32 + c4 * 2 + 1] = __floats2half2_rn(m.z, m.w);
    }
    __syncthreads();

    const int c    = z * 4 + ty;              // chunk index
    const int base = 35 * c;                  // first output row of chunk
    const __half2 HINF = __float2half2_rn(CUDART_INF_F);

    if (base < HH) {
        const int lb = 35 * ty + 17;          // smem row of 'base'

        // Pass 1: suffix minima
        __half2 S[35];
        __half2 run = HINF;
        #pragma unroll
        for (int k = 0; k < 52; k++) {
            if (k == 35) run = HINF;
            run = __hmin2(run, sm[(lb + 34 - k) * 32 + tx]);
            if (k >= 17) S[51 - k] = run;
        }

        // Pass 2: prefix minima, combine; stage TRANSPOSED into st
        run = HINF;
        #pragma unroll
        for (int k = 0; k < 52; k++) {
            if (k == 35) run = HINF;
            run = __hmin2(run, sm[(lb + k) * 32 + tx]);
            if (k >= 17) {
                int i = base + k - 17;
                if (i < HH) {
                    int hl = 35 * ty + k - 17;  // h - 140z
                    __half2 c2 = __hmin2(S[k - 17], run);
                    st[(2 * tx) * 142 + hl]     = __low2half(c2);
                    st[(2 * tx + 1) * 142 + hl] = __high2half(c2);
                }
            }
        }
    }
    __syncthreads();

    // Write-out: warp handles w columns (warpid + 4k); lanes = consecutive hp
    // -> coalesced STG.32 of h-pair half2.
    {
        const int hp0   = z * 70;
        const int hpLim = (HH / 2 - hp0 < 70) ? (HH / 2 - hp0) : 70;
        __half2* dst = g_tT + ((size_t)(b * WW + wc0)) * (HH / 2);
        for (int w = ty; w < 64; w += 4) {
            for (int hp = tx; hp < hpLim; hp += 32) {
                unsigned v = *(const unsigned*)&st[w * 142 + 2 * hp];
                dst[(size_t)w * (HH / 2) + hp0 + hp] = *(__half2*)&v;
            }
        }
    }
}

// ---------------------------------------------------------------------------
// Kernel 2: horizontal min-filter, NO smem tile. Thread pairs (lane 2q =
// suffix role, 2q+1 = prefix role) each run one 52-step chain reading
// g_tT[b][w][hp] directly (predicated LDG, L2-resident), then exchange via
// shfl_xor(1) and combine. half2 packs 2 image rows (h-pair).
// 128-thr blocks; 64 chain-pairs per block; (b, chunk) uniform per block.
// grid = 960 blocks (16 B * 15 chunks * 256 hp * 2 roles / 128).
// ---------------------------------------------------------------------------
__global__ __launch_bounds__(128) void k2_horiz(float* __restrict__ out) {
    __shared__ float red[128];
    __shared__ int isLast;

    const int tid = threadIdx.x;
    const int gt  = blockIdx.x * 128 + tid;
    const int r   = gt & 1;                   // 0 = suffix role, 1 = prefix role
    const int pi  = gt >> 1;                  // chain index
    const int hp  = pi & 255;
    const int rest = pi >> 8;                 // 0..239, uniform per block
    const int c   = rest % 15;
    const int b   = rest / 15;
    const int base = 35 * c;
    const __half2 HINF2 = __float2half2_rn(CUDART_INF_F);

    const __half2* col = g_tT + ((size_t)b * WW) * (HH / 2) + hp;

    // One 52-step running-min chain per thread; results kept in registers.
    // role 0 stores suffix minima at A[51-k]; role 1 prefix minima at A[k-17].
    __half2 A[35];
    __half2 run = HINF2;
    #pragma unroll
    for (int k = 0; k < 52; k++) {
        if (k == 35) run = HINF2;
        int w = r ? (base + k) : (base + 34 - k);
        __half2 v = HINF2;
        if ((unsigned)w < WW) v = col[(size_t)w * (HH / 2)];
        run = __hmin2(run, v);
        if (k >= 17) {
            if (r) A[k - 17] = run;
            else   A[51 - k] = run;
        }
    }

    // Exchange + combine: out[j] = min(S[j], P[j]).
    // role 0 produces j = 0..17 (always valid: base+17 <= 507),
    // role 1 produces j = 18..34 (guard base+j < 512 for last chunk).
    __half2 hacc = __float2half2_rn(0.0f);
    #pragma unroll
    for (int t = 0; t < 18; t++) {
        __half2 send = r ? A[t] : (t < 17 ? A[18 + t] : A[34]);
        unsigned su = *(unsigned*)&send;
        unsigned ru = __shfl_xor_sync(0xffffffffu, su, 1);
        __half2 other = *(__half2*)&ru;
        if (r == 0) {
            hacc = __hadd2(hacc, __hmin2(A[t], other));      // j = t
        } else if (t < 17) {
            int j = 18 + t;
            if (base + j < WW)
                hacc = __hadd2(hacc, __hmin2(other, A[j]));  // j = 18+t
        }
    }
    float2 e2 = __half22float2(hacc);
    float acc = e2.x + e2.y;

    // Deterministic in-block reduction (128 threads)
    red[tid] = acc;
    __syncthreads();
    #pragma unroll
    for (int s = 64; s > 0; s >>= 1) {
        if (tid < s) red[tid] += red[tid + s];
        __syncthreads();
    }
    if (tid == 0) {
        g_partial[blockIdx.x] = red[0];
        __threadfence();
        int done = atomicAdd(&g_count, 1);
        isLast = (done == 959) ? 1 : 0;
    }
    __syncthreads();

    // Last block: deterministic final reduction over the 960 partials
    if (isLast) {
        float v = 0.0f;
        #pragma unroll
        for (int i = 0; i < 8; i++) {
            int idx = tid + i * 128;
            if (idx < 960) v += g_partial[idx];
        }
        red[tid] = v;
        __syncthreads();
        #pragma unroll
        for (int s = 64; s > 0; s >>= 1) {
            if (tid < s) red[tid] += red[tid + s];
            __syncthreads();
        }
        if (tid == 0) {
            out[0] = red[0] * (1.0f / 4194304.0f) - 1.0f;
            g_count = 0;   // reset for next graph replay
        }
    }
}

extern "C" void kernel_launch(void* const* d_in, const int* in_sizes, int n_in,
                              void* d_out, int out_size) {
    const float* x = (const float*)d_in[0];
    float* out = (float*)d_out;

    k1_vert<<<dim3(WW / 64, BB, 4), dim3(32, 4)>>>(x);
    k2_horiz<<<960, 128>>>(out);
}

// round 9
// speedup vs baseline: 1.7451x; 1.7451x over previous
#include <cuda_runtime.h>
#include <cuda_fp16.h>
#include <math_constants.h>

#define HH 512
#define WW 512
#define BB 16
// window p=35, pad=17
// loss = mean(erosion_35x35(min_c x)) - 1   (erosion = separable min filter)

// Intermediate: vertically eroded field, [B][H][W/2], half2 packs (w, w+1)
__device__ __align__(16) __half2 g_t2[BB * HH * WW / 2];
// Per-block partial sums from kernel 2 (1024 blocks)
__device__ float g_partial[1024];
// Completion counter for fused final reduction (reset each run)
__device__ int g_count;

// ---------------------------------------------------------------------------
// Kernel 1 (UNCHANGED round-4 form — measured at the memory roofline):
// channel-min of x (fp32 -> fp16) fused with vertical min-filter,
// van Herk chunk 35, half2 packed along W.
// Block = (32 lanes, 4 chunks) = 128 thr; grid = (W/64, B, 4).
// ---------------------------------------------------------------------------
__global__ __launch_bounds__(128) void k1_vert(const float* __restrict__ x) {
    __shared__ __half2 sm[174 * 32];

    const int tx  = threadIdx.x;
    const int ty  = threadIdx.y;
    const int tid = ty * 32 + tx;
    const int wc0 = blockIdx.x * 64;
    const int b   = blockIdx.y;
    const int z   = blockIdx.z;
    const int r0  = z * 140;                 // 4 chunks * 35 rows per z-group
    const float INF = CUDART_INF_F;

    const float* xb = x + (size_t)b * 3 * HH * WW;
    for (int j = tid; j < 174 * 16; j += 128) {
        int r  = j >> 4;
        int c4 = j & 15;
        int gh = r0 - 17 + r;
        float4 m;
        if ((unsigned)gh < HH) {
            const float4* p = (const float4*)(xb + (size_t)gh * WW + wc0 + c4 * 4);
            float4 a0 = p[0];
            float4 a1 = p[(HH * WW) / 4];
            float4 a2 = p[(2 * HH * WW) / 4];
            m.x = fminf(a0.x, fminf(a1.x, a2.x));
            m.y = fminf(a0.y, fminf(a1.y, a2.y));
            m.z = fminf(a0.z, fminf(a1.z, a2.z));
            m.w = fminf(a0.w, fminf(a1.w, a2.w));
        } else {
            m = make_float4(INF, INF, INF, INF);
        }
        sm[r * 32 + c4 * 2]     = __floats2half2_rn(m.x, m.y);
        sm[r * 32 + c4 * 2 + 1] = __floats2half2_rn(m.z, m.w);
    }
    __syncthreads();

    const int c    = z * 4 + ty;
    const int base = 35 * c;
    if (base >= HH) return;
    const int lb = 35 * ty + 17;
    const __half2 HINF = __float2half2_rn(CUDART_INF_F);

    __half2 S[35];
    __half2 run = HINF;
    #pragma unroll
    for (int k = 0; k < 52; k++) {
        if (k == 35) run = HINF;
        run = __hmin2(run, sm[(lb + 34 - k) * 32 + tx]);
        if (k >= 17) S[51 - k] = run;
    }

    run = HINF;
    const size_t ob = (size_t)b * HH;
    const int wcol = (wc0 >> 1) + tx;
    #pragma unroll
    for (int k = 0; k < 52; k++) {
        if (k == 35) run = HINF;
        run = __hmin2(run, sm[(lb + k) * 32 + tx]);
        if (k >= 17) {
            int i = base + k - 17;
            if (i < HH)
                g_t2[(ob + i) * (WW / 2) + wcol] = __hmin2(S[k - 17], run);
        }
    }
}

// ---------------------------------------------------------------------------
// Kernel 2: horizontal min-filter in PAIR DOMAIN with chunk length 36
// (even -> pairs aligned to chunks). Each thread = one image row, one chunk
// slot t (t = tx-1 in [-1, 14]): suffix pair-minima over chunk t (18 steps)
// + prefix pair-minima over chunk t+1 (18 steps) + parity combine.
//   Suf(2u)   = hmin(SR[u]);  Suf(2u+1) = min(SR[u].hi, hmin(SR[u+1]))
//   Pre(2v)   = min(R[v].lo, R[v-1].hi);  Pre(2v+1) = hmin(R[v])
//   out[36t+18+2n]   = min(SR[n].hi, H_S[n+1], H_P[n-1])
//   out[36t+18+2n+1] = min(H_S[n+1], R[n].lo,  R[n-1].hi)
// Tile: straight copy of g_t2 rows + INF borders (no clamping in chains),
// layout [pair-slot][row] pitch 9 -> conflict-free chain LDS.
// Block = (16 slots, 8 rows) = 128 thr; grid = (H/8, B) = 1024 blocks.
// ---------------------------------------------------------------------------
__global__ __launch_bounds__(128) void k2_horiz(float* __restrict__ out) {
    __shared__ __half2 smt[306 * 9];          // slots: [0,18) INF | 18+pc | [274,306) INF
    __shared__ float red[128];
    __shared__ int isLast;

    const int tx  = threadIdx.x;              // chunk slot 0..15
    const int ty  = threadIdx.y;              // row-in-tile 0..7
    const int tid = ty * 16 + tx;
    const int h0  = blockIdx.x * 8;
    const int b   = blockIdx.y;
    const __half2 HINF2 = __float2half2_rn(CUDART_INF_F);

    // INF borders: pair-slots [0,18) and [274,306): 50 slots x 8 rows
    for (int j = tid; j < 400; j += 128) {
        int sl = j >> 3;                      // 0..49
        int r  = j & 7;
        int s  = (sl < 18) ? sl : (sl + 256);
        smt[s * 9 + r] = HINF2;
    }
    // Main data: 8 rows x 64 uint4, coalesced LDG.128, scattered STS.32
    {
        const uint4* src = (const uint4*)(g_t2 + ((size_t)b * HH + h0) * (WW / 2));
        #pragma unroll
        for (int i = 0; i < 4; i++) {
            int idx = tid + i * 128;          // = row*64 + uint4-slot
            int r   = idx >> 6;
            int c4  = (idx & 63) * 4;         // half2 pair index
            uint4 v = src[idx];
            smt[(c4 + 18) * 9 + r] = *(__half2*)&v.x;
            smt[(c4 + 19) * 9 + r] = *(__half2*)&v.y;
            smt[(c4 + 20) * 9 + r] = *(__half2*)&v.z;
            smt[(c4 + 21) * 9 + r] = *(__half2*)&v.w;
        }
    }
    __syncthreads();

    const int t = tx - 1;                     // -1..14 (slot 15 fully masked)

    // Backward: suffix pair-minima over chunk t (tile slots 18t+u+18)
    __half2 SR[18];
    {
        __half2 run = HINF2;
        #pragma unroll
        for (int u = 17; u >= 0; u--) {
            run = __hmin2(run, smt[(18 * t + u + 18) * 9 + ty]);
            SR[u] = run;
        }
    }

    // Forward over chunk t+1 (tile slots 18t+n+36) + combine + accumulate
    __half2 hacc = __float2half2_rn(0.0f);
    __half2 Rp  = HINF2;                      // R[n-1]
    __half2 HPp = HINF2;                      // hmin(R[n-1]) broadcast
    const int obase = 36 * t + 18;
    #pragma unroll
    for (int n = 0; n < 18; n++) {
        __half2 v  = smt[(18 * t + n + 36) * 9 + ty];
        __half2 Rc = __hmin2(Rp, v);          // R[n]
        __half2 srn = (n < 17) ? SR[n + 1] : HINF2;
        unsigned srnu = *(unsigned*)&srn;
        unsigned swp  = __byte_perm(srnu, srnu, 0x1032);
        __half2 hs = __hmin2(srn, *(__half2*)&swp);   // H_S[n+1] broadcast
        unsigned sru = *(unsigned*)&SR[n];
        unsigned Rcu = *(unsigned*)&Rc;
        unsigned Rpu = *(unsigned*)&Rp;
        unsigned HPu = *(unsigned*)&HPp;
        unsigned Au = __byte_perm(sru, Rcu, 0x5432);  // (SR[n].hi, Rc.lo)
        unsigned Bu = __byte_perm(HPu, Rpu, 0x7610);  // (HPp,      Rp.hi)
        __half2 o = __hmin2(__hmin2(*(__half2*)&Au, *(__half2*)&Bu), hs);
        if ((unsigned)(obase + 2 * n) < 512u)
            hacc = __hadd2(hacc, o);
        unsigned rs = __byte_perm(Rcu, Rcu, 0x1032);
        HPp = __hmin2(Rc, *(__half2*)&rs);    // hmin(R[n]) broadcast
        Rp = Rc;
    }
    float2 e2 = __half22float2(hacc);
    float acc = e2.x + e2.y;

    // Deterministic in-block reduction (128 threads)
    red[tid] = acc;
    __syncthreads();
    #pragma unroll
    for (int s = 64; s > 0; s >>= 1) {
        if (tid < s) red[tid] += red[tid + s];
        __syncthreads();
    }
    if (tid == 0) {
        g_partial[b * 64 + blockIdx.x] = red[0];
        __threadfence();
        int done = atomicAdd(&g_count, 1);
        isLast = (done == 1023) ? 1 : 0;
    }
    __syncthreads();

    // Last block: deterministic final reduction over the 1024 partials
    if (isLast) {
        float v = 0.0f;
        #pragma unroll
        for (int i = 0; i < 8; i++) v += g_partial[tid + i * 128];
        red[tid] = v;
        __syncthreads();
        #pragma unroll
        for (int s = 64; s > 0; s >>= 1) {
            if (tid < s) red[tid] += red[tid + s];
            __syncthreads();
        }
        if (tid == 0) {
            out[0] = red[0] * (1.0f / 4194304.0f) - 1.0f;
            g_count = 0;   // reset for next graph replay
        }
    }
}

extern "C" void kernel_launch(void* const* d_in, const int* in_sizes, int n_in,
                              void* d_out, int out_size) {
    const float* x = (const float*)d_in[0];
    float* out = (float*)d_out;

    k1_vert<<<dim3(WW / 64, BB, 4), dim3(32, 4)>>>(x);
    k2_horiz<<<dim3(HH / 8, BB), dim3(16, 8)>>>(out);
}